// round 11
// baseline (speedup 1.0000x reference)
#include <cuda_runtime.h>
#include <cstdint>
#include <cmath>

#define B_SZ   64
#define KCP    16
#define NDIM   19            // K + 3
#define NPAD   20            // padded coeff rows per batch (16B alignment)
#define HH     512
#define WW     512
#define HWPIX  (HH * WW)
#define PAIRS  (HWPIX / 2)   // 131072 pixel pairs, 1 per thread

// inv_delta[:, :16] passed by value (computed on host — input-independent).
struct InvW {
    float w[NDIM][KCP];
};

// Producer -> consumer mailbox (one-wave grid; flag memset to 0 per launch).
__device__ float2 g_coeff[B_SZ * NPAD];
__device__ int    g_flag;

// ---------------------------------------------------------------------------
// Packed f32x2 helpers (sm_103a).
// ---------------------------------------------------------------------------
__device__ __forceinline__ unsigned long long pack2(float lo, float hi) {
    unsigned long long r;
    asm("mov.b64 %0, {%1, %2};" : "=l"(r) : "f"(lo), "f"(hi));
    return r;
}
__device__ __forceinline__ unsigned long long fma2(unsigned long long a,
                                                   unsigned long long b,
                                                   unsigned long long c) {
    unsigned long long d;
    asm("fma.rn.f32x2 %0, %1, %2, %3;" : "=l"(d) : "l"(a), "l"(b), "l"(c));
    return d;
}
__device__ __forceinline__ unsigned long long add2(unsigned long long a,
                                                   unsigned long long b) {
    unsigned long long d;
    asm("add.rn.f32x2 %0, %1, %2;" : "=l"(d) : "l"(a), "l"(b));
    return d;
}

// ---------------------------------------------------------------------------
// One kernel, 513 blocks. Block 0 = coeff producer; blocks 1..512 = pixel
// blocks running R5's roofline-proven main loop with a zero-register-cost
// prologue (basis -> tid0 spin -> 10KB L2 copy -> sync).
// ---------------------------------------------------------------------------
__global__ void __launch_bounds__(256, 4) tps_kernel(
    InvW inv, const float* __restrict__ sp, ulonglong2* __restrict__ out) {

    const int tid = threadIdx.x;

    if (blockIdx.x == 0) {
        // ---- producer: coeff[b][i][d] = sum_j invW[i][j] * sp[b][j][d] ----
        #pragma unroll
        for (int m = 0; m < 5; m++) {
            const int t = m * 256 + tid;          // 0..1279
            if (t < B_SZ * NDIM) {
                const int b = t / NDIM;
                const int i = t - b * NDIM;
                const float2* spb = reinterpret_cast<const float2*>(sp) + b * KCP;
                float ax = 0.0f, ay = 0.0f;
                #pragma unroll
                for (int j = 0; j < KCP; j++) {
                    const float  w = inv.w[i][j];
                    const float2 s = spb[j];
                    ax = fmaf(w, s.x, ax);
                    ay = fmaf(w, s.y, ay);
                }
                g_coeff[b * NPAD + i] = make_float2(ax, ay);
            } else {
                g_coeff[(t - B_SZ * NDIM) * NPAD + NDIM] = make_float2(0.0f, 0.0f);
            }
        }
        __syncthreads();
        __threadfence();
        if (tid == 0) atomicExch(&g_flag, 1);     // release
        return;
    }

    // ---- pixel blocks ----
    __shared__ __align__(16) float2 s_coeff[B_SZ * NPAD];  // 10 KB

    const int t  = (blockIdx.x - 1) * 256 + tid;  // pixel-pair index
    const int n0 = t * 2;
    const int w0 = n0 & (WW - 1);
    const int h  = n0 >> 9;
    const float X0 = fmaf((float)w0, 2.0f / (float)(WW - 1), -1.0f);
    const float X1 = X0 + 2.0f / (float)(WW - 1);
    const float Y  = fmaf((float)h, 2.0f / (float)(HH - 1), -1.0f);

    // Basis first (no dependency on coeffs) — overlaps the producer.
    unsigned long long u0[KCP], u1[KCP];
    #pragma unroll
    for (int k = 0; k < KCP; k++) {
        const float cx = -1.0f + (float)(k >> 2) * (2.0f / 3.0f);
        const float cy = -1.0f + (float)(k & 3) * (2.0f / 3.0f);
        const float dy  = Y - cy;
        const float dy2 = dy * dy;
        {
            float dx = X0 - cx;
            float r2 = fmaf(dx, dx, dy2);
            float u  = r2 * __logf(r2 + 1e-6f);
            u0[k] = pack2(u, u);
        }
        {
            float dx = X1 - cx;
            float r2 = fmaf(dx, dx, dy2);
            float u  = r2 * __logf(r2 + 1e-6f);
            u1[k] = pack2(u, u);
        }
    }
    const unsigned long long X0d = pack2(X0, X0);
    const unsigned long long X1d = pack2(X1, X1);
    const unsigned long long Yd  = pack2(Y, Y);

    // Wait for producer (tid0 only), then stage coeffs smem-side.
    if (tid == 0) {
        volatile int* f = &g_flag;
        while (*f == 0) { }
        __threadfence();                          // acquire
    }
    __syncthreads();
    {
        const float4* src = reinterpret_cast<const float4*>(g_coeff);
        float4* dst = reinterpret_cast<float4*>(s_coeff);
        #pragma unroll
        for (int m = 0; m < 3; m++) {
            const int i = m * 256 + tid;
            if (i < (B_SZ * NPAD) / 2) dst[i] = src[i];
        }
    }
    __syncthreads();

    // ---- R5 main loop (at f32x2-issue roofline) ----
    #pragma unroll 4
    for (int b = 0; b < B_SZ; b++) {
        const ulonglong2* cc = reinterpret_cast<const ulonglong2*>(s_coeff + b * NPAD);
        // Affine part: rows 16 (const), 17 (x), 18 (y)
        const ulonglong2 c8 = cc[8];   // rows 16, 17
        const ulonglong2 c9 = cc[9];   // rows 18, pad
        unsigned long long a0 = fma2(X0d, c8.y, c8.x);
        unsigned long long a1 = fma2(X1d, c8.y, c8.x);
        a0 = fma2(Yd, c9.x, a0);
        a1 = fma2(Yd, c9.x, a1);
        unsigned long long b0 = 0ULL, b1 = 0ULL;
        #pragma unroll
        for (int j = 0; j < 8; j++) {
            const ulonglong2 c = cc[j];           // rows 2j, 2j+1 (broadcast LDS.128)
            a0 = fma2(u0[2 * j + 0], c.x, a0);
            b0 = fma2(u0[2 * j + 1], c.y, b0);
            a1 = fma2(u1[2 * j + 0], c.x, a1);
            b1 = fma2(u1[2 * j + 1], c.y, b1);
        }
        ulonglong2 r;
        r.x = add2(a0, b0);
        r.y = add2(a1, b1);
        out[(size_t)b * PAIRS + t] = r;           // STG.128
    }
}

// ---------------------------------------------------------------------------
// Host: build delta(19x19), invert (Gauss-Jordan, partial pivoting, fp64).
// Input-independent -> runs on CPU at capture time; rides in as kernel param.
// ---------------------------------------------------------------------------
static inline double h_cpx(int k) { return -1.0 + (double)(k >> 2) * (2.0 / 3.0); }
static inline double h_cpy(int k) { return -1.0 + (double)(k & 3) * (2.0 / 3.0); }

static void build_invw(InvW* out) {
    double M[NDIM][2 * NDIM];
    for (int r = 0; r < NDIM; r++)
        for (int c = 0; c < 2 * NDIM; c++) {
            double v = 0.0;
            if (c >= NDIM) {
                v = (c - NDIM == r) ? 1.0 : 0.0;
            } else if (r < KCP && c < KCP) {
                double dx = h_cpx(r) - h_cpx(c);
                double dy = h_cpy(r) - h_cpy(c);
                double r2 = dx * dx + dy * dy;
                v = r2 * log(r2 + 1e-6);
            } else if (r < KCP) {
                v = (c == KCP) ? 1.0 : ((c == KCP + 1) ? h_cpx(r) : h_cpy(r));
            } else if (c < KCP) {
                v = (r == KCP) ? 1.0 : ((r == KCP + 1) ? h_cpx(c) : h_cpy(c));
            }
            M[r][c] = v;
        }

    for (int p = 0; p < NDIM; p++) {
        int best = p;
        double bm = fabs(M[p][p]);
        for (int r = p + 1; r < NDIM; r++) {
            double m = fabs(M[r][p]);
            if (m > bm) { bm = m; best = r; }
        }
        if (best != p)
            for (int c = 0; c < 2 * NDIM; c++) {
                double tv = M[p][c]; M[p][c] = M[best][c]; M[best][c] = tv;
            }
        const double inv = 1.0 / M[p][p];
        for (int c = 0; c < 2 * NDIM; c++) M[p][c] *= inv;
        for (int r = 0; r < NDIM; r++) {
            if (r == p) continue;
            const double f = M[r][p];
            if (f == 0.0) continue;
            for (int c = 0; c < 2 * NDIM; c++) M[r][c] -= f * M[p][c];
        }
    }

    for (int i = 0; i < NDIM; i++)
        for (int j = 0; j < KCP; j++)
            out->w[i][j] = (float)M[i][NDIM + j];
}

// ---------------------------------------------------------------------------
extern "C" void kernel_launch(void* const* d_in, const int* in_sizes, int n_in,
                              void* d_out, int out_size) {
    const float* sp = (const float*)d_in[0];        // [64, 16, 2] fp32
    ulonglong2* out = (ulonglong2*)d_out;           // [64, 512, 512, 2] fp32

    InvW inv;
    build_invw(&inv);                               // host-side, capture-time only

    // Reset the producer flag every launch (graph-capturable memset node).
    void* flag_addr = nullptr;
    cudaGetSymbolAddress(&flag_addr, g_flag);
    cudaMemsetAsync(flag_addr, 0, sizeof(int));

    tps_kernel<<<1 + PAIRS / 256, 256>>>(inv, sp, out);
}

// round 12
// speedup vs baseline: 1.2438x; 1.2438x over previous
#include <cuda_runtime.h>
#include <cstdint>
#include <cmath>

#define B_SZ   64
#define KCP    16
#define NDIM   19            // K + 3
#define NSLOT  20            // slots 0..15 RBF, 16 const, 17 X, 18 Y, 19 pad
#define HH     512
#define WW     512
#define HWPIX  (HH * WW)
#define PAIRS  (HWPIX / 2)   // 131072 pixel pairs, 1 per thread

// inv_delta[:, :16] passed by value (computed on host — input-independent).
struct InvW {
    float w[NDIM][KCP];
};

// ---------------------------------------------------------------------------
// Packed f32x2 helpers (sm_103a).
// ---------------------------------------------------------------------------
__device__ __forceinline__ unsigned long long pack2(float lo, float hi) {
    unsigned long long r;
    asm("mov.b64 %0, {%1, %2};" : "=l"(r) : "f"(lo), "f"(hi));
    return r;
}
__device__ __forceinline__ unsigned long long fma2(unsigned long long a,
                                                   unsigned long long b,
                                                   unsigned long long c) {
    unsigned long long d;
    asm("fma.rn.f32x2 %0, %1, %2, %3;" : "=l"(d) : "l"(a), "l"(b), "l"(c));
    return d;
}
// Free unpack: names the two 32-bit halves of the 64-bit pair.
__device__ __forceinline__ float2 unpk(unsigned long long a) {
    float2 f;
    asm("mov.b64 {%0, %1}, %2;" : "=f"(f.x), "=f"(f.y) : "l"(a));
    return f;
}

// ---------------------------------------------------------------------------
// Fused kernel, K-packed basis (40 regs, no spills):
//   u[m] = (v[2m], v[2m+1]) per pixel; coeffs per dim K-packed in smem.
//   Per batch: 10 broadcast LDS.128 + 40 fma2 (4 indep chains) + 4 FADD + STG.128.
// ---------------------------------------------------------------------------
__global__ void __launch_bounds__(256, 4) tps_fused_kernel(
    InvW inv, const float* __restrict__ sp, float4* __restrict__ out) {

    __shared__ __align__(16) float s_cx[B_SZ][NSLOT];   // 5 KB
    __shared__ __align__(16) float s_cy[B_SZ][NSLOT];   // 5 KB
    __shared__ __align__(16) float s_w[NDIM][KCP];      // 1.2 KB

    const int tid = threadIdx.x;

    // Stage invW into shared (304 floats = 76 float4).
    {
        const float4* wsrc = reinterpret_cast<const float4*>(&inv.w[0][0]);
        float4* wdst = reinterpret_cast<float4*>(&s_w[0][0]);
        if (tid < (NDIM * KCP) / 4) wdst[tid] = wsrc[tid];
    }
    __syncthreads();

    // Coeff prologue (warp-uniform rows, broadcast LDS weights, sp from L2).
    {
        const int b = tid & 63;
        const int q = tid >> 6;
        const float2* spb = reinterpret_cast<const float2*>(sp) + b * KCP;
        float accx[5] = {0.f, 0.f, 0.f, 0.f, 0.f};
        float accy[5] = {0.f, 0.f, 0.f, 0.f, 0.f};
        #pragma unroll
        for (int j = 0; j < KCP; j++) {
            const float2 s = spb[j];                 // LDG.64 (L2-resident)
            #pragma unroll
            for (int m = 0; m < 5; m++) {
                const int i = q + 4 * m;
                if (i < NDIM) {
                    const float w = s_w[i][j];       // broadcast LDS
                    accx[m] = fmaf(w, s.x, accx[m]);
                    accy[m] = fmaf(w, s.y, accy[m]);
                }
            }
        }
        #pragma unroll
        for (int m = 0; m < 5; m++) {
            const int i = q + 4 * m;                 // i==19 -> pad zeros
            s_cx[b][i] = (i < NDIM) ? accx[m] : 0.0f;
            s_cy[b][i] = (i < NDIM) ? accy[m] : 0.0f;
        }
    }

    // ---- basis (independent of coeffs; overlaps other warps' prologue) ----
    const int t  = blockIdx.x * 256 + tid;           // pixel-pair index
    const int n0 = t * 2;
    const int w0 = n0 & (WW - 1);
    const int h  = n0 >> 9;
    const float X0 = fmaf((float)w0, 2.0f / (float)(WW - 1), -1.0f);
    const float X1 = X0 + 2.0f / (float)(WW - 1);
    const float Y  = fmaf((float)h, 2.0f / (float)(HH - 1), -1.0f);

    // Packed basis: u[m] = (v[2m], v[2m+1]); slots 16..19 = (1, X), (Y, 0).
    unsigned long long u0[NSLOT / 2], u1[NSLOT / 2];
    #pragma unroll
    for (int m = 0; m < 8; m++) {
        const int k0 = 2 * m, k1 = 2 * m + 1;
        const float cx0 = -1.0f + (float)(k0 >> 2) * (2.0f / 3.0f);
        const float cy0 = -1.0f + (float)(k0 & 3) * (2.0f / 3.0f);
        const float cx1 = -1.0f + (float)(k1 >> 2) * (2.0f / 3.0f);
        const float cy1 = -1.0f + (float)(k1 & 3) * (2.0f / 3.0f);
        const float dy0 = Y - cy0, dy1 = Y - cy1;
        const float dy0sq = dy0 * dy0, dy1sq = dy1 * dy1;

        float dxa0 = X0 - cx0, dxa1 = X0 - cx1;
        float ra0 = fmaf(dxa0, dxa0, dy0sq);
        float ra1 = fmaf(dxa1, dxa1, dy1sq);
        u0[m] = pack2(ra0 * __logf(ra0 + 1e-6f), ra1 * __logf(ra1 + 1e-6f));

        float dxb0 = X1 - cx0, dxb1 = X1 - cx1;
        float rb0 = fmaf(dxb0, dxb0, dy0sq);
        float rb1 = fmaf(dxb1, dxb1, dy1sq);
        u1[m] = pack2(rb0 * __logf(rb0 + 1e-6f), rb1 * __logf(rb1 + 1e-6f));
    }
    u0[8] = pack2(1.0f, X0);
    u1[8] = pack2(1.0f, X1);
    u0[9] = pack2(Y, 0.0f);
    u1[9] = u0[9];

    __syncthreads();

    // ---- main loop: 64 batches ----
    #pragma unroll 4
    for (int b = 0; b < B_SZ; b++) {
        const ulonglong2* cxp = reinterpret_cast<const ulonglong2*>(&s_cx[b][0]);
        const ulonglong2* cyp = reinterpret_cast<const ulonglong2*>(&s_cy[b][0]);
        unsigned long long ax0 = 0ULL, ay0 = 0ULL, ax1 = 0ULL, ay1 = 0ULL;
        #pragma unroll
        for (int m = 0; m < 5; m++) {
            const ulonglong2 qx = cxp[m];            // broadcast LDS.128
            const ulonglong2 qy = cyp[m];            // broadcast LDS.128
            ax0 = fma2(u0[2 * m + 0], qx.x, ax0);
            ax0 = fma2(u0[2 * m + 1], qx.y, ax0);
            ay0 = fma2(u0[2 * m + 0], qy.x, ay0);
            ay0 = fma2(u0[2 * m + 1], qy.y, ay0);
            ax1 = fma2(u1[2 * m + 0], qx.x, ax1);
            ax1 = fma2(u1[2 * m + 1], qx.y, ax1);
            ay1 = fma2(u1[2 * m + 0], qy.x, ay1);
            ay1 = fma2(u1[2 * m + 1], qy.y, ay1);
        }
        const float2 px0 = unpk(ax0);
        const float2 py0 = unpk(ay0);
        const float2 px1 = unpk(ax1);
        const float2 py1 = unpk(ay1);
        float4 r;
        r.x = px0.x + px0.y;                         // x @ pixel 0
        r.y = py0.x + py0.y;                         // y @ pixel 0
        r.z = px1.x + px1.y;                         // x @ pixel 1
        r.w = py1.x + py1.y;                         // y @ pixel 1
        out[(size_t)b * PAIRS + t] = r;              // STG.128
    }
}

// ---------------------------------------------------------------------------
// Host: build delta(19x19), invert (Gauss-Jordan, partial pivoting, fp64).
// Input-independent -> runs on CPU at capture time; rides in as kernel param.
// ---------------------------------------------------------------------------
static inline double h_cpx(int k) { return -1.0 + (double)(k >> 2) * (2.0 / 3.0); }
static inline double h_cpy(int k) { return -1.0 + (double)(k & 3) * (2.0 / 3.0); }

static void build_invw(InvW* out) {
    double M[NDIM][2 * NDIM];
    for (int r = 0; r < NDIM; r++)
        for (int c = 0; c < 2 * NDIM; c++) {
            double v = 0.0;
            if (c >= NDIM) {
                v = (c - NDIM == r) ? 1.0 : 0.0;
            } else if (r < KCP && c < KCP) {
                double dx = h_cpx(r) - h_cpx(c);
                double dy = h_cpy(r) - h_cpy(c);
                double r2 = dx * dx + dy * dy;
                v = r2 * log(r2 + 1e-6);
            } else if (r < KCP) {
                v = (c == KCP) ? 1.0 : ((c == KCP + 1) ? h_cpx(r) : h_cpy(r));
            } else if (c < KCP) {
                v = (r == KCP) ? 1.0 : ((r == KCP + 1) ? h_cpx(c) : h_cpy(c));
            }
            M[r][c] = v;
        }

    for (int p = 0; p < NDIM; p++) {
        int best = p;
        double bm = fabs(M[p][p]);
        for (int r = p + 1; r < NDIM; r++) {
            double m = fabs(M[r][p]);
            if (m > bm) { bm = m; best = r; }
        }
        if (best != p)
            for (int c = 0; c < 2 * NDIM; c++) {
                double tv = M[p][c]; M[p][c] = M[best][c]; M[best][c] = tv;
            }
        const double inv = 1.0 / M[p][p];
        for (int c = 0; c < 2 * NDIM; c++) M[p][c] *= inv;
        for (int r = 0; r < NDIM; r++) {
            if (r == p) continue;
            const double f = M[r][p];
            if (f == 0.0) continue;
            for (int c = 0; c < 2 * NDIM; c++) M[r][c] -= f * M[p][c];
        }
    }

    for (int i = 0; i < NDIM; i++)
        for (int j = 0; j < KCP; j++)
            out->w[i][j] = (float)M[i][NDIM + j];
}

// ---------------------------------------------------------------------------
extern "C" void kernel_launch(void* const* d_in, const int* in_sizes, int n_in,
                              void* d_out, int out_size) {
    const float* sp = (const float*)d_in[0];        // [64, 16, 2] fp32
    float4* out = (float4*)d_out;                   // [64, 512, 512, 2] fp32

    InvW inv;
    build_invw(&inv);                               // host-side, capture-time only

    tps_fused_kernel<<<PAIRS / 256, 256>>>(inv, sp, out);
}

// round 13
// speedup vs baseline: 1.5509x; 1.2469x over previous
#include <cuda_runtime.h>
#include <cstdint>
#include <cmath>

#define B_SZ   64
#define KCP    16
#define NDIM   19            // K + 3
#define NPAD   20            // padded coeff rows per batch (16B alignment)
#define HH     512
#define WW     512
#define HWPIX  (HH * WW)
#define PAIRS  (HWPIX / 2)   // 131072 pixel pairs, 1 per thread

// inv_delta[:, :16] passed by value (computed on host — input-independent).
struct InvW {
    float w[NDIM][KCP];
};

// ---------------------------------------------------------------------------
// Packed f32x2 helpers (sm_103a).
// ---------------------------------------------------------------------------
__device__ __forceinline__ unsigned long long pack2(float lo, float hi) {
    unsigned long long r;
    asm("mov.b64 %0, {%1, %2};" : "=l"(r) : "f"(lo), "f"(hi));
    return r;
}
__device__ __forceinline__ unsigned long long fma2(unsigned long long a,
                                                   unsigned long long b,
                                                   unsigned long long c) {
    unsigned long long d;
    asm("fma.rn.f32x2 %0, %1, %2, %3;" : "=l"(d) : "l"(a), "l"(b), "l"(c));
    return d;
}
__device__ __forceinline__ unsigned long long add2(unsigned long long a,
                                                   unsigned long long b) {
    unsigned long long d;
    asm("add.rn.f32x2 %0, %1, %2;" : "=l"(d) : "l"(a), "l"(b));
    return d;
}

// ---------------------------------------------------------------------------
// R10 champion kernel, with the register cap relaxed: 3 blocks/SM -> 85-reg
// budget so the duplicated-lane basis (64 regs) lives entirely in RF.
// Trade: grid 512 > 444 slots => 1.15 waves, but zero spill traffic in the
// 64-iteration hot loop.
// ---------------------------------------------------------------------------
__global__ void __launch_bounds__(256, 3) tps_fused_kernel(
    InvW inv, const float* __restrict__ sp, ulonglong2* __restrict__ out) {

    __shared__ __align__(16) float2 s_coeff[B_SZ * NPAD];  // 10 KB
    __shared__ __align__(16) float s_w[NDIM][KCP];         // 1.2 KB

    const int tid = threadIdx.x;

    // Stage invW into shared (304 floats = 76 float4; one-shot).
    {
        const float4* wsrc = reinterpret_cast<const float4*>(&inv.w[0][0]);
        float4* wdst = reinterpret_cast<float4*>(&s_w[0][0]);
        if (tid < (NDIM * KCP) / 4) wdst[tid] = wsrc[tid];
    }
    __syncthreads();

    // Coeff prologue: thread t -> batch b = t&63, row-group q = t>>6 (warp-
    // uniform). Rows i = q + 4m, m = 0..4 (q=3,m=4 -> pad row 19).
    {
        const int b = tid & 63;
        const int q = tid >> 6;
        const float2* spb = reinterpret_cast<const float2*>(sp) + b * KCP;
        float accx[5] = {0.f, 0.f, 0.f, 0.f, 0.f};
        float accy[5] = {0.f, 0.f, 0.f, 0.f, 0.f};
        #pragma unroll
        for (int j = 0; j < KCP; j++) {
            const float2 s = spb[j];                 // LDG.64 (L2-resident)
            #pragma unroll
            for (int m = 0; m < 5; m++) {
                const int i = q + 4 * m;
                if (i < NDIM) {
                    const float w = s_w[i][j];       // broadcast LDS
                    accx[m] = fmaf(w, s.x, accx[m]);
                    accy[m] = fmaf(w, s.y, accy[m]);
                }
            }
        }
        #pragma unroll
        for (int m = 0; m < 5; m++) {
            const int i = q + 4 * m;
            s_coeff[b * NPAD + i] =
                (i < NDIM) ? make_float2(accx[m], accy[m]) : make_float2(0.f, 0.f);
        }
    }
    __syncthreads();

    // ---- per-thread pixel pair ----
    const int t  = blockIdx.x * 256 + tid;
    const int n0 = t * 2;
    const int w0 = n0 & (WW - 1);
    const int h  = n0 >> 9;
    const float X0 = fmaf((float)w0, 2.0f / (float)(WW - 1), -1.0f);
    const float X1 = X0 + 2.0f / (float)(WW - 1);
    const float Y  = fmaf((float)h, 2.0f / (float)(HH - 1), -1.0f);

    unsigned long long u0[KCP], u1[KCP];
    #pragma unroll
    for (int k = 0; k < KCP; k++) {
        const float cx = -1.0f + (float)(k >> 2) * (2.0f / 3.0f);
        const float cy = -1.0f + (float)(k & 3) * (2.0f / 3.0f);
        const float dy  = Y - cy;
        const float dy2 = dy * dy;
        {
            float dx = X0 - cx;
            float r2 = fmaf(dx, dx, dy2);
            float u  = r2 * __logf(r2 + 1e-6f);
            u0[k] = pack2(u, u);
        }
        {
            float dx = X1 - cx;
            float r2 = fmaf(dx, dx, dy2);
            float u  = r2 * __logf(r2 + 1e-6f);
            u1[k] = pack2(u, u);
        }
    }
    const unsigned long long X0d = pack2(X0, X0);
    const unsigned long long X1d = pack2(X1, X1);
    const unsigned long long Yd  = pack2(Y, Y);

    #pragma unroll 4
    for (int b = 0; b < B_SZ; b++) {
        const ulonglong2* cc = reinterpret_cast<const ulonglong2*>(s_coeff + b * NPAD);
        // Affine part: rows 16 (const), 17 (x), 18 (y)
        const ulonglong2 c8 = cc[8];   // rows 16, 17
        const ulonglong2 c9 = cc[9];   // rows 18, pad
        unsigned long long a0 = fma2(X0d, c8.y, c8.x);
        unsigned long long a1 = fma2(X1d, c8.y, c8.x);
        a0 = fma2(Yd, c9.x, a0);
        a1 = fma2(Yd, c9.x, a1);
        unsigned long long b0 = 0ULL, b1 = 0ULL;
        #pragma unroll
        for (int j = 0; j < 8; j++) {
            const ulonglong2 c = cc[j];           // rows 2j, 2j+1 (broadcast LDS.128)
            a0 = fma2(u0[2 * j + 0], c.x, a0);
            b0 = fma2(u0[2 * j + 1], c.y, b0);
            a1 = fma2(u1[2 * j + 0], c.x, a1);
            b1 = fma2(u1[2 * j + 1], c.y, b1);
        }
        ulonglong2 r;
        r.x = add2(a0, b0);
        r.y = add2(a1, b1);
        out[(size_t)b * PAIRS + t] = r;           // STG.128
    }
}

// ---------------------------------------------------------------------------
// Host: build delta(19x19), invert (Gauss-Jordan, partial pivoting, fp64).
// Input-independent -> runs on CPU at capture time; rides in as kernel param.
// ---------------------------------------------------------------------------
static inline double h_cpx(int k) { return -1.0 + (double)(k >> 2) * (2.0 / 3.0); }
static inline double h_cpy(int k) { return -1.0 + (double)(k & 3) * (2.0 / 3.0); }

static void build_invw(InvW* out) {
    double M[NDIM][2 * NDIM];
    for (int r = 0; r < NDIM; r++)
        for (int c = 0; c < 2 * NDIM; c++) {
            double v = 0.0;
            if (c >= NDIM) {
                v = (c - NDIM == r) ? 1.0 : 0.0;
            } else if (r < KCP && c < KCP) {
                double dx = h_cpx(r) - h_cpx(c);
                double dy = h_cpy(r) - h_cpy(c);
                double r2 = dx * dx + dy * dy;
                v = r2 * log(r2 + 1e-6);
            } else if (r < KCP) {
                v = (c == KCP) ? 1.0 : ((c == KCP + 1) ? h_cpx(r) : h_cpy(r));
            } else if (c < KCP) {
                v = (r == KCP) ? 1.0 : ((r == KCP + 1) ? h_cpx(c) : h_cpy(c));
            }
            M[r][c] = v;
        }

    for (int p = 0; p < NDIM; p++) {
        int best = p;
        double bm = fabs(M[p][p]);
        for (int r = p + 1; r < NDIM; r++) {
            double m = fabs(M[r][p]);
            if (m > bm) { bm = m; best = r; }
        }
        if (best != p)
            for (int c = 0; c < 2 * NDIM; c++) {
                double tv = M[p][c]; M[p][c] = M[best][c]; M[best][c] = tv;
            }
        const double inv = 1.0 / M[p][p];
        for (int c = 0; c < 2 * NDIM; c++) M[p][c] *= inv;
        for (int r = 0; r < NDIM; r++) {
            if (r == p) continue;
            const double f = M[r][p];
            if (f == 0.0) continue;
            for (int c = 0; c < 2 * NDIM; c++) M[r][c] -= f * M[p][c];
        }
    }

    for (int i = 0; i < NDIM; i++)
        for (int j = 0; j < KCP; j++)
            out->w[i][j] = (float)M[i][NDIM + j];
}

// ---------------------------------------------------------------------------
extern "C" void kernel_launch(void* const* d_in, const int* in_sizes, int n_in,
                              void* d_out, int out_size) {
    const float* sp = (const float*)d_in[0];        // [64, 16, 2] fp32
    ulonglong2* out = (ulonglong2*)d_out;           // [64, 512, 512, 2] fp32

    InvW inv;
    build_invw(&inv);                               // host-side, capture-time only

    tps_fused_kernel<<<PAIRS / 256, 256>>>(inv, sp, out);
}